// round 1
// baseline (speedup 1.0000x reference)
#include <cuda_runtime.h>
#include <math.h>

#define LSEQ   4096
#define NSTATE 64
#define NPAIR  2048      // 16*256/2
#define TPB    512

static __device__ double2 g_K[LSEQ];
static __device__ float2  g_Ksp[LSEQ];

// ---------------- complex double helpers (setup only) ----------------
struct cd { double x, y; };
__device__ __forceinline__ cd cdadd(cd a, cd b){ return {a.x+b.x, a.y+b.y}; }
__device__ __forceinline__ cd cdsub(cd a, cd b){ return {a.x-b.x, a.y-b.y}; }
__device__ __forceinline__ cd cdmul(cd a, cd b){ return {a.x*b.x - a.y*b.y, a.x*b.y + a.y*b.x}; }
__device__ __forceinline__ cd cddiv(cd a, cd b){
    double d = b.x*b.x + b.y*b.y;
    return {(a.x*b.x + a.y*b.y)/d, (a.y*b.x - a.x*b.y)/d};
}

// K[k] = c * (k00 - k01*k10/(1+k11)) at Omega_k = exp(-2*pi*i*k/L), step=0.001
__global__ void compute_K_kernel(const float* __restrict__ lre, const float* __restrict__ lim,
                                 const float* __restrict__ pre, const float* __restrict__ pim,
                                 const float* __restrict__ bre, const float* __restrict__ bim,
                                 const float* __restrict__ cre, const float* __restrict__ cim)
{
    int k = blockIdx.x * blockDim.x + threadIdx.x;
    if (k >= LSEQ) return;
    const double PI_D = 3.14159265358979323846;
    double ang = -2.0 * PI_D * (double)k / (double)LSEQ;
    double sn, cs;
    sincos(ang, &sn, &cs);
    cd Om  = {cs, sn};
    cd one = {1.0, 0.0};
    cd opo = cdadd(one, Om);                    // 1 + Omega
    cd g   = cddiv(cdsub(one, Om), opo);
    g.x *= 2000.0; g.y *= 2000.0;               // (2/step)
    cd c   = cddiv((cd){2.0, 0.0}, opo);

    cd k00 = {0,0}, k01 = {0,0}, k10 = {0,0}, k11 = {0,0};
    #pragma unroll 4
    for (int n = 0; n < NSTATE; n++) {
        cd lam = {(double)lre[n], (double)lim[n]};
        cd P   = {(double)pre[n], (double)pim[n]};
        cd B   = {(double)bre[n], (double)bim[n]};
        cd Cc  = {(double)cre[n], -(double)cim[n]};
        cd Pc  = {P.x, -P.y};
        cd den = cddiv(one, cdsub(g, lam));
        k00 = cdadd(k00, cdmul(den, cdmul(Cc, B)));
        k01 = cdadd(k01, cdmul(den, cdmul(Cc, P)));
        k10 = cdadd(k10, cdmul(den, cdmul(Pc, B)));
        k11 = cdadd(k11, cdmul(den, cdmul(Pc, P)));
    }
    cd corr = cddiv(cdmul(k01, k10), cdadd(one, k11));
    cd K    = cdmul(c, cdsub(k00, corr));
    g_K[k]  = make_double2(K.x, K.y);
}

// Ksp[idx] = (K[k] + conj(K[-k]))/2 / L   with k = digitrev8_4(idx)
__global__ void compute_Ksp_kernel()
{
    int idx = blockIdx.x * blockDim.x + threadIdx.x;
    if (idx >= LSEQ) return;
    int k = ((idx & 7) << 9) | (((idx >> 3) & 7) << 6) |
            (((idx >> 6) & 7) << 3) | ((idx >> 9) & 7);
    double2 Ka = g_K[k];
    double2 Kb = g_K[(LSEQ - k) & (LSEQ - 1)];
    const double sc = 0.5 / (double)LSEQ;
    g_Ksp[idx] = make_float2((float)((Ka.x + Kb.x) * sc),
                             (float)((Ka.y - Kb.y) * sc));
}

// ---------------- fp32 FFT machinery ----------------
#define SIDX(i) ((i) + ((i) >> 3))   // pad every 8 floats -> conflict-light

__device__ __forceinline__ float2 f2add(float2 a, float2 b){ return make_float2(a.x+b.x, a.y+b.y); }
__device__ __forceinline__ float2 f2sub(float2 a, float2 b){ return make_float2(a.x-b.x, a.y-b.y); }
__device__ __forceinline__ float2 cmulf(float2 a, float2 b){
    return make_float2(fmaf(a.x, b.x, -a.y*b.y), fmaf(a.x, b.y, a.y*b.x));
}
template<int SGN>
__device__ __forceinline__ float2 mul_is(float2 z){  // z * (i*SGN)
    return (SGN > 0) ? make_float2(-z.y, z.x) : make_float2(z.y, -z.x);
}

// 8-point DFT:  out[k] = sum_b in[b] * w8^(SGN*k*b), natural order in/out, unscaled.
template<int SGN>
__device__ __forceinline__ void dft8(float2* v)
{
    const float C = 0.70710678118654752440f;
    const float S = (float)SGN;
    float2 u0 = f2add(v[0], v[4]), w0 = f2sub(v[0], v[4]);
    float2 u1 = f2add(v[1], v[5]), w1 = f2sub(v[1], v[5]);
    float2 u2 = f2add(v[2], v[6]), w2 = f2sub(v[2], v[6]);
    float2 u3 = f2add(v[3], v[7]), w3 = f2sub(v[3], v[7]);
    // twiddle odd branch: w1 *= w8^S, w2 *= i*S, w3 *= w8^(3S)
    w1 = make_float2(C * (w1.x - S * w1.y),  C * (S * w1.x + w1.y));
    w2 = mul_is<SGN>(w2);
    w3 = make_float2(-C * (w3.x + S * w3.y), C * (S * w3.x - w3.y));
    // even 4-pt
    float2 p0 = f2add(u0, u2), q0 = f2sub(u0, u2);
    float2 p1 = f2add(u1, u3), q1 = mul_is<SGN>(f2sub(u1, u3));
    v[0] = f2add(p0, p1); v[4] = f2sub(p0, p1);
    v[2] = f2add(q0, q1); v[6] = f2sub(q0, q1);
    // odd 4-pt
    float2 r0 = f2add(w0, w2), s0 = f2sub(w0, w2);
    float2 r1 = f2add(w1, w3), s1 = mul_is<SGN>(f2sub(w1, w3));
    v[1] = f2add(r0, r1); v[5] = f2sub(r0, r1);
    v[3] = f2add(s0, s1); v[7] = f2sub(s0, s1);
}

// apply w_M^(SGN*a*j) to v[j], j=1..7 (iterated powers of one __sincosf)
template<int SGN, int M>
__device__ __forceinline__ void twiddles(float2* v, int a)
{
    const float kAng = (float)SGN * 6.283185307179586f / (float)M;
    float sn, cs;
    __sincosf(kAng * (float)a, &sn, &cs);
    float2 w1 = make_float2(cs, sn);
    float2 w  = w1;
    v[1] = cmulf(v[1], w);
    #pragma unroll
    for (int j = 2; j < 8; j++) { w = cmulf(w, w1); v[j] = cmulf(v[j], w); }
}

// one radix-8 pass in shared memory (in-place per thread).
// SGN=-1: forward DIF (butterfly then twiddle). SGN=+1: inverse of that stage
// (twiddle then butterfly). H = butterfly stride, M = 8H = sub-transform size.
template<int SGN, int H>
__device__ __forceinline__ void stage_sh(float* s_re, float* s_im, int t)
{
    const int M = 8 * H;
    int base = (t / H) * M + (t % H);
    int a    = t % H;
    float2 v[8];
    #pragma unroll
    for (int i = 0; i < 8; i++) {
        int idx = base + H * i;
        v[i] = make_float2(s_re[SIDX(idx)], s_im[SIDX(idx)]);
    }
    if (SGN < 0) { dft8<SGN>(v); twiddles<SGN, M>(v, a); }
    else         { twiddles<SGN, M>(v, a); dft8<SGN>(v); }
    #pragma unroll
    for (int i = 0; i < 8; i++) {
        int idx = base + H * i;
        s_re[SIDX(idx)] = v[i].x; s_im[SIDX(idx)] = v[i].y;
    }
}

// ---------------- main kernel: 2 real channels per block ----------------
__global__ __launch_bounds__(TPB, 2)
void s4_fftconv_kernel(const float* __restrict__ x, float* __restrict__ y)
{
    __shared__ float s_re[LSEQ + (LSEQ >> 3)];
    __shared__ float s_im[LSEQ + (LSEQ >> 3)];
    const int t = threadIdx.x;
    const size_t base = (size_t)blockIdx.x * 2u * LSEQ;
    const float* x1 = x + base;
    const float* x2 = x + base + LSEQ;
    float* y1 = y + base;
    float* y2 = y + base + LSEQ;

    float2 v[8];

    // ---- forward stage 0 (M=4096, H=512): read global, write shared
    #pragma unroll
    for (int b = 0; b < 8; b++)
        v[b] = make_float2(x1[t + 512 * b], x2[t + 512 * b]);
    dft8<-1>(v);
    twiddles<-1, 4096>(v, t);
    #pragma unroll
    for (int j = 0; j < 8; j++) {
        int idx = t + 512 * j;
        s_re[SIDX(idx)] = v[j].x; s_im[SIDX(idx)] = v[j].y;
    }
    __syncthreads();

    stage_sh<-1, 64>(s_re, s_im, t);   // forward stage 1 (M=512)
    __syncthreads();
    stage_sh<-1, 8>(s_re, s_im, t);    // forward stage 2 (M=64)
    __syncthreads();

    // ---- fused: fwd stage 3 (H=1, a=0) + pointwise Ksp + inv stage 3 — all in regs
    {
        const int i0 = 8 * t;
        #pragma unroll
        for (int j = 0; j < 8; j++) {
            int idx = i0 + j;
            v[j] = make_float2(s_re[SIDX(idx)], s_im[SIDX(idx)]);
        }
        dft8<-1>(v);
        #pragma unroll
        for (int j = 0; j < 8; j++)
            v[j] = cmulf(v[j], g_Ksp[i0 + j]);
        dft8<1>(v);
        #pragma unroll
        for (int b = 0; b < 8; b++) {
            int idx = i0 + b;
            s_re[SIDX(idx)] = v[b].x; s_im[SIDX(idx)] = v[b].y;
        }
    }
    __syncthreads();

    stage_sh<1, 8>(s_re, s_im, t);     // inverse stage 2
    __syncthreads();
    stage_sh<1, 64>(s_re, s_im, t);    // inverse stage 1
    __syncthreads();

    // ---- inverse stage 0 (M=4096, H=512): read shared, write global
    #pragma unroll
    for (int j = 0; j < 8; j++) {
        int idx = t + 512 * j;
        v[j] = make_float2(s_re[SIDX(idx)], s_im[SIDX(idx)]);
    }
    twiddles<1, 4096>(v, t);
    dft8<1>(v);
    #pragma unroll
    for (int b = 0; b < 8; b++) {
        y1[t + 512 * b] = v[b].x;   // channel 2p
        y2[t + 512 * b] = v[b].y;   // channel 2p+1
    }
}

extern "C" void kernel_launch(void* const* d_in, const int* in_sizes, int n_in,
                              void* d_out, int out_size)
{
    const float* x   = (const float*)d_in[0];
    const float* lre = (const float*)d_in[1];
    const float* lim = (const float*)d_in[2];
    const float* pre = (const float*)d_in[3];
    const float* pim = (const float*)d_in[4];
    const float* bre = (const float*)d_in[5];
    const float* bim = (const float*)d_in[6];
    const float* cre = (const float*)d_in[7];
    const float* cim = (const float*)d_in[8];
    float* y = (float*)d_out;

    compute_K_kernel<<<LSEQ / 128, 128>>>(lre, lim, pre, pim, bre, bim, cre, cim);
    compute_Ksp_kernel<<<LSEQ / 128, 128>>>();
    s4_fftconv_kernel<<<NPAIR, TPB>>>(x, y);
}

// round 2
// speedup vs baseline: 3.1788x; 3.1788x over previous
#include <cuda_runtime.h>
#include <math.h>

#define LSEQ   4096
#define NSTATE 64
#define NPAIR  2048      // 16*256/2
#define TPB    512

static __device__ float2 g_K[LSEQ];
static __device__ float2 g_Ksp[LSEQ];

// ---------------- compute K (all fp32; g and c via tan identity) ----------------
// g = i*2000*tan(pi*k/L),  c = 1 + i*tan(pi*k/L)
// 8 lanes per k; each lane handles 8 states; shfl-xor reduction.
__global__ void compute_K_kernel(const float* __restrict__ lre, const float* __restrict__ lim,
                                 const float* __restrict__ pre, const float* __restrict__ pim,
                                 const float* __restrict__ bre, const float* __restrict__ bim,
                                 const float* __restrict__ cre, const float* __restrict__ cim)
{
    int gtid = blockIdx.x * blockDim.x + threadIdx.x;   // 32768 total
    int k   = gtid >> 3;
    int sub = gtid & 7;
    if (k >= LSEQ) return;

    const float h = (float)k * 7.6699039394282221e-4f;  // pi/4096
    const float t = tanf(h);
    const float G = 2000.0f * t;

    float k00r = 0.f, k00i = 0.f, k01r = 0.f, k01i = 0.f;
    float k10r = 0.f, k10i = 0.f, k11r = 0.f, k11i = 0.f;

    #pragma unroll
    for (int j = 0; j < 8; j++) {
        int n = sub * 8 + j;
        float lr = lre[n], li = lim[n];
        float pr = pre[n], pi_ = pim[n];
        float br = bre[n], bi = bim[n];
        float cr = cre[n], ci = cim[n];

        float ex = -lr;
        float ey = G - li;
        float d  = fmaf(ex, ex, ey * ey);
        float r  = 1.0f / d;
        float dr = ex * r;
        float di = -ey * r;

        // numerators: nb = conj(C)*B, np = conj(C)*P, pb = conj(P)*B, pp = |P|^2 (real)
        float nbr = fmaf(cr, br,  ci * bi),  nbi = fmaf(cr, bi, -ci * br);
        float npr = fmaf(cr, pr,  ci * pi_), npi = fmaf(cr, pi_, -ci * pr);
        float pbr = fmaf(pr, br,  pi_ * bi), pbi = fmaf(pr, bi, -pi_ * br);
        float pp  = fmaf(pr, pr,  pi_ * pi_);

        k00r = fmaf(dr, nbr, fmaf(-di, nbi, k00r));
        k00i = fmaf(dr, nbi, fmaf( di, nbr, k00i));
        k01r = fmaf(dr, npr, fmaf(-di, npi, k01r));
        k01i = fmaf(dr, npi, fmaf( di, npr, k01i));
        k10r = fmaf(dr, pbr, fmaf(-di, pbi, k10r));
        k10i = fmaf(dr, pbi, fmaf( di, pbr, k10i));
        k11r = fmaf(dr, pp, k11r);
        k11i = fmaf(di, pp, k11i);
    }

    // reduce 8 lanes -> lane sub==0
    #pragma unroll
    for (int m = 1; m < 8; m <<= 1) {
        k00r += __shfl_xor_sync(0xffffffffu, k00r, m);
        k00i += __shfl_xor_sync(0xffffffffu, k00i, m);
        k01r += __shfl_xor_sync(0xffffffffu, k01r, m);
        k01i += __shfl_xor_sync(0xffffffffu, k01i, m);
        k10r += __shfl_xor_sync(0xffffffffu, k10r, m);
        k10i += __shfl_xor_sync(0xffffffffu, k10i, m);
        k11r += __shfl_xor_sync(0xffffffffu, k11r, m);
        k11i += __shfl_xor_sync(0xffffffffu, k11i, m);
    }

    if (sub == 0) {
        // corr = k01*k10 / (1 + k11)
        float numr = k01r * k10r - k01i * k10i;
        float numi = k01r * k10i + k01i * k10r;
        float der  = 1.0f + k11r;
        float dei  = k11i;
        float dd   = 1.0f / fmaf(der, der, dei * dei);
        float cor_r = (numr * der + numi * dei) * dd;
        float cor_i = (numi * der - numr * dei) * dd;
        float ar = k00r - cor_r;
        float ai = k00i - cor_i;
        // K = (1 + i*t) * (ar + i*ai)
        g_K[k] = make_float2(fmaf(-t, ai, ar), fmaf(t, ar, ai));
    }
}

// Ksp[idx] = (K[k] + conj(K[-k]))/2 / L   with k = digitrev8_4(idx)
__global__ void compute_Ksp_kernel()
{
    int idx = blockIdx.x * blockDim.x + threadIdx.x;
    if (idx >= LSEQ) return;
    int k = ((idx & 7) << 9) | (((idx >> 3) & 7) << 6) |
            (((idx >> 6) & 7) << 3) | ((idx >> 9) & 7);
    float2 Ka = g_K[k];
    float2 Kb = g_K[(LSEQ - k) & (LSEQ - 1)];
    const float sc = 0.5f / (float)LSEQ;
    g_Ksp[idx] = make_float2((Ka.x + Kb.x) * sc, (Ka.y - Kb.y) * sc);
}

// ---------------- fp32 FFT machinery ----------------
#define SIDX(i) ((i) + ((i) >> 3))   // pad every 8 floats -> conflict-light

__device__ __forceinline__ float2 f2add(float2 a, float2 b){ return make_float2(a.x+b.x, a.y+b.y); }
__device__ __forceinline__ float2 f2sub(float2 a, float2 b){ return make_float2(a.x-b.x, a.y-b.y); }
__device__ __forceinline__ float2 cmulf(float2 a, float2 b){
    return make_float2(fmaf(a.x, b.x, -a.y*b.y), fmaf(a.x, b.y, a.y*b.x));
}
template<int SGN>
__device__ __forceinline__ float2 mul_is(float2 z){  // z * (i*SGN)
    return (SGN > 0) ? make_float2(-z.y, z.x) : make_float2(z.y, -z.x);
}

// 8-point DFT:  out[k] = sum_b in[b] * w8^(SGN*k*b), natural order in/out, unscaled.
template<int SGN>
__device__ __forceinline__ void dft8(float2* v)
{
    const float C = 0.70710678118654752440f;
    const float S = (float)SGN;
    float2 u0 = f2add(v[0], v[4]), w0 = f2sub(v[0], v[4]);
    float2 u1 = f2add(v[1], v[5]), w1 = f2sub(v[1], v[5]);
    float2 u2 = f2add(v[2], v[6]), w2 = f2sub(v[2], v[6]);
    float2 u3 = f2add(v[3], v[7]), w3 = f2sub(v[3], v[7]);
    w1 = make_float2(C * (w1.x - S * w1.y),  C * (S * w1.x + w1.y));
    w2 = mul_is<SGN>(w2);
    w3 = make_float2(-C * (w3.x + S * w3.y), C * (S * w3.x - w3.y));
    float2 p0 = f2add(u0, u2), q0 = f2sub(u0, u2);
    float2 p1 = f2add(u1, u3), q1 = mul_is<SGN>(f2sub(u1, u3));
    v[0] = f2add(p0, p1); v[4] = f2sub(p0, p1);
    v[2] = f2add(q0, q1); v[6] = f2sub(q0, q1);
    float2 r0 = f2add(w0, w2), s0 = f2sub(w0, w2);
    float2 r1 = f2add(w1, w3), s1 = mul_is<SGN>(f2sub(w1, w3));
    v[1] = f2add(r0, r1); v[5] = f2sub(r0, r1);
    v[3] = f2add(s0, s1); v[7] = f2sub(s0, s1);
}

// apply w_M^(SGN*a*j) to v[j], j=1..7 (iterated powers of one __sincosf)
template<int SGN, int M>
__device__ __forceinline__ void twiddles(float2* v, int a)
{
    const float kAng = (float)SGN * 6.283185307179586f / (float)M;
    float sn, cs;
    __sincosf(kAng * (float)a, &sn, &cs);
    float2 w1 = make_float2(cs, sn);
    float2 w  = w1;
    v[1] = cmulf(v[1], w);
    #pragma unroll
    for (int j = 2; j < 8; j++) { w = cmulf(w, w1); v[j] = cmulf(v[j], w); }
}

// one radix-8 pass in shared memory (in-place per thread).
template<int SGN, int H>
__device__ __forceinline__ void stage_sh(float* s_re, float* s_im, int t)
{
    const int M = 8 * H;
    int base = (t / H) * M + (t % H);
    int a    = t % H;
    float2 v[8];
    #pragma unroll
    for (int i = 0; i < 8; i++) {
        int idx = base + H * i;
        v[i] = make_float2(s_re[SIDX(idx)], s_im[SIDX(idx)]);
    }
    if (SGN < 0) { dft8<SGN>(v); twiddles<SGN, M>(v, a); }
    else         { twiddles<SGN, M>(v, a); dft8<SGN>(v); }
    #pragma unroll
    for (int i = 0; i < 8; i++) {
        int idx = base + H * i;
        s_re[SIDX(idx)] = v[i].x; s_im[SIDX(idx)] = v[i].y;
    }
}

// ---------------- main kernel: 2 real channels per block ----------------
__global__ __launch_bounds__(TPB, 2)
void s4_fftconv_kernel(const float* __restrict__ x, float* __restrict__ y)
{
    __shared__ float s_re[LSEQ + (LSEQ >> 3)];
    __shared__ float s_im[LSEQ + (LSEQ >> 3)];
    const int t = threadIdx.x;
    const size_t base = (size_t)blockIdx.x * 2u * LSEQ;
    const float* x1 = x + base;
    const float* x2 = x + base + LSEQ;
    float* y1 = y + base;
    float* y2 = y + base + LSEQ;

    float2 v[8];

    // ---- forward stage 0 (M=4096, H=512): read global, write shared
    #pragma unroll
    for (int b = 0; b < 8; b++)
        v[b] = make_float2(x1[t + 512 * b], x2[t + 512 * b]);
    dft8<-1>(v);
    twiddles<-1, 4096>(v, t);
    #pragma unroll
    for (int j = 0; j < 8; j++) {
        int idx = t + 512 * j;
        s_re[SIDX(idx)] = v[j].x; s_im[SIDX(idx)] = v[j].y;
    }
    __syncthreads();

    stage_sh<-1, 64>(s_re, s_im, t);   // forward stage 1 (M=512)
    __syncthreads();
    stage_sh<-1, 8>(s_re, s_im, t);    // forward stage 2 (M=64)
    __syncthreads();

    // ---- fused: fwd stage 3 (H=1, a=0) + pointwise Ksp + inv stage 3 — all in regs
    {
        const int i0 = 8 * t;
        #pragma unroll
        for (int j = 0; j < 8; j++) {
            int idx = i0 + j;
            v[j] = make_float2(s_re[SIDX(idx)], s_im[SIDX(idx)]);
        }
        dft8<-1>(v);
        #pragma unroll
        for (int j = 0; j < 8; j++)
            v[j] = cmulf(v[j], g_Ksp[i0 + j]);
        dft8<1>(v);
        #pragma unroll
        for (int b = 0; b < 8; b++) {
            int idx = i0 + b;
            s_re[SIDX(idx)] = v[b].x; s_im[SIDX(idx)] = v[b].y;
        }
    }
    __syncthreads();

    stage_sh<1, 8>(s_re, s_im, t);     // inverse stage 2
    __syncthreads();
    stage_sh<1, 64>(s_re, s_im, t);    // inverse stage 1
    __syncthreads();

    // ---- inverse stage 0 (M=4096, H=512): read shared, write global
    #pragma unroll
    for (int j = 0; j < 8; j++) {
        int idx = t + 512 * j;
        v[j] = make_float2(s_re[SIDX(idx)], s_im[SIDX(idx)]);
    }
    twiddles<1, 4096>(v, t);
    dft8<1>(v);
    #pragma unroll
    for (int b = 0; b < 8; b++) {
        y1[t + 512 * b] = v[b].x;   // channel 2p
        y2[t + 512 * b] = v[b].y;   // channel 2p+1
    }
}

extern "C" void kernel_launch(void* const* d_in, const int* in_sizes, int n_in,
                              void* d_out, int out_size)
{
    const float* x   = (const float*)d_in[0];
    const float* lre = (const float*)d_in[1];
    const float* lim = (const float*)d_in[2];
    const float* pre = (const float*)d_in[3];
    const float* pim = (const float*)d_in[4];
    const float* bre = (const float*)d_in[5];
    const float* bim = (const float*)d_in[6];
    const float* cre = (const float*)d_in[7];
    const float* cim = (const float*)d_in[8];
    float* y = (float*)d_out;

    compute_K_kernel<<<(LSEQ * 8) / 256, 256>>>(lre, lim, pre, pim, bre, bim, cre, cim);
    compute_Ksp_kernel<<<LSEQ / 128, 128>>>();
    s4_fftconv_kernel<<<NPAIR, TPB>>>(x, y);
}

// round 3
// speedup vs baseline: 3.4398x; 1.0821x over previous
#include <cuda_runtime.h>
#include <math.h>

#define LSEQ   4096
#define NSTATE 64
#define NPAIR  2048      // 16*256/2
#define TPB    512

static __device__ float2 g_Ksp[LSEQ];

__device__ __forceinline__ int digitrev84(int i) {
    return ((i & 7) << 9) | (((i >> 3) & 7) << 6) |
           (((i >> 6) & 7) << 3) | ((i >> 9) & 7);
}

// ---------------- fused K + Ksp kernel (all fp32) ----------------
// g(k) = i*2000*tan(pi*k/L), c(k) = 1 + i*tan(pi*k/L).
// Each 8-lane group handles k and its mirror m = L-k (t_m = -t_k), sharing
// all numerators. Lane 0 writes Ksp[rev(k)] and Ksp[rev(m)] = conj(...).
__global__ void compute_K_fused(const float* __restrict__ lre, const float* __restrict__ lim,
                                const float* __restrict__ pre, const float* __restrict__ pim,
                                const float* __restrict__ bre, const float* __restrict__ bim,
                                const float* __restrict__ cre, const float* __restrict__ cim)
{
    int gtid = blockIdx.x * blockDim.x + threadIdx.x;
    int k    = gtid >> 3;           // 0..2048
    int sub  = gtid & 7;
    if (k > LSEQ / 2) return;

    const float t = tanf((float)k * 7.6699039394282221e-4f);  // pi/4096
    const float G = 2000.0f * t;

    // accumulators: a* for k (+G), b* for mirror (-G)
    float a00r=0,a00i=0,a01r=0,a01i=0,a10r=0,a10i=0,a11r=0,a11i=0;
    float b00r=0,b00i=0,b01r=0,b01i=0,b10r=0,b10i=0,b11r=0,b11i=0;

    #pragma unroll
    for (int j = 0; j < 8; j++) {
        int n = sub * 8 + j;
        float lr = lre[n], li = lim[n];
        float pr = pre[n], pi_ = pim[n];
        float br = bre[n], bi = bim[n];
        float cr = cre[n], ci = cim[n];

        float nbr = fmaf(cr, br,  ci * bi),  nbi = fmaf(cr, bi, -ci * br);
        float npr = fmaf(cr, pr,  ci * pi_), npi = fmaf(cr, pi_, -ci * pr);
        float pbr = fmaf(pr, br,  pi_ * bi), pbi = fmaf(pr, bi, -pi_ * br);
        float pp  = fmaf(pr, pr,  pi_ * pi_);

        // den for k: 1/((-lr) + i(G-li))
        {
            float ex = -lr, ey = G - li;
            float r  = 1.0f / fmaf(ex, ex, ey * ey);
            float dr = ex * r, di = -ey * r;
            a00r = fmaf(dr, nbr, fmaf(-di, nbi, a00r));
            a00i = fmaf(dr, nbi, fmaf( di, nbr, a00i));
            a01r = fmaf(dr, npr, fmaf(-di, npi, a01r));
            a01i = fmaf(dr, npi, fmaf( di, npr, a01i));
            a10r = fmaf(dr, pbr, fmaf(-di, pbi, a10r));
            a10i = fmaf(dr, pbi, fmaf( di, pbr, a10i));
            a11r = fmaf(dr, pp, a11r);
            a11i = fmaf(di, pp, a11i);
        }
        // den for mirror: G -> -G
        {
            float ex = -lr, ey = -G - li;
            float r  = 1.0f / fmaf(ex, ex, ey * ey);
            float dr = ex * r, di = -ey * r;
            b00r = fmaf(dr, nbr, fmaf(-di, nbi, b00r));
            b00i = fmaf(dr, nbi, fmaf( di, nbr, b00i));
            b01r = fmaf(dr, npr, fmaf(-di, npi, b01r));
            b01i = fmaf(dr, npi, fmaf( di, npr, b01i));
            b10r = fmaf(dr, pbr, fmaf(-di, pbi, b10r));
            b10i = fmaf(dr, pbi, fmaf( di, pbr, b10i));
            b11r = fmaf(dr, pp, b11r);
            b11i = fmaf(di, pp, b11i);
        }
    }

    #pragma unroll
    for (int m = 1; m < 8; m <<= 1) {
        a00r += __shfl_xor_sync(0xffffffffu, a00r, m);
        a00i += __shfl_xor_sync(0xffffffffu, a00i, m);
        a01r += __shfl_xor_sync(0xffffffffu, a01r, m);
        a01i += __shfl_xor_sync(0xffffffffu, a01i, m);
        a10r += __shfl_xor_sync(0xffffffffu, a10r, m);
        a10i += __shfl_xor_sync(0xffffffffu, a10i, m);
        a11r += __shfl_xor_sync(0xffffffffu, a11r, m);
        a11i += __shfl_xor_sync(0xffffffffu, a11i, m);
        b00r += __shfl_xor_sync(0xffffffffu, b00r, m);
        b00i += __shfl_xor_sync(0xffffffffu, b00i, m);
        b01r += __shfl_xor_sync(0xffffffffu, b01r, m);
        b01i += __shfl_xor_sync(0xffffffffu, b01i, m);
        b10r += __shfl_xor_sync(0xffffffffu, b10r, m);
        b10i += __shfl_xor_sync(0xffffffffu, b10i, m);
        b11r += __shfl_xor_sync(0xffffffffu, b11r, m);
        b11i += __shfl_xor_sync(0xffffffffu, b11i, m);
    }

    if (sub == 0) {
        // K(k):  (1 + i t) * (k00 - k01*k10/(1+k11))
        float Kk_r, Kk_i, Km_r, Km_i;
        {
            float numr = a01r * a10r - a01i * a10i;
            float numi = a01r * a10i + a01i * a10r;
            float der  = 1.0f + a11r, dei = a11i;
            float dd   = 1.0f / fmaf(der, der, dei * dei);
            float ar = a00r - (numr * der + numi * dei) * dd;
            float ai = a00i - (numi * der - numr * dei) * dd;
            Kk_r = fmaf(-t, ai, ar); Kk_i = fmaf(t, ar, ai);
        }
        {
            float numr = b01r * b10r - b01i * b10i;
            float numi = b01r * b10i + b01i * b10r;
            float der  = 1.0f + b11r, dei = b11i;
            float dd   = 1.0f / fmaf(der, der, dei * dei);
            float ar = b00r - (numr * der + numi * dei) * dd;
            float ai = b00i - (numi * der - numr * dei) * dd;
            // K(m) = (1 - i t) * (...)
            Km_r = fmaf(t, ai, ar); Km_i = fmaf(-t, ar, ai);
        }
        const float sc = 0.5f / (float)LSEQ;
        float sr = (Kk_r + Km_r) * sc;
        float si = (Kk_i - Km_i) * sc;
        int mk = (LSEQ - k) & (LSEQ - 1);
        g_Ksp[digitrev84(k)]  = make_float2(sr,  si);
        g_Ksp[digitrev84(mk)] = make_float2(sr, -si);
    }
}

// ---------------- fp32 FFT machinery ----------------
#define SIDX(i) ((i) + ((i) >> 3))   // pad every 8 complex -> conflict-light

__device__ __forceinline__ float2 f2add(float2 a, float2 b){ return make_float2(a.x+b.x, a.y+b.y); }
__device__ __forceinline__ float2 f2sub(float2 a, float2 b){ return make_float2(a.x-b.x, a.y-b.y); }
__device__ __forceinline__ float2 cmulf(float2 a, float2 b){
    return make_float2(fmaf(a.x, b.x, -a.y*b.y), fmaf(a.x, b.y, a.y*b.x));
}
template<int SGN>
__device__ __forceinline__ float2 mul_is(float2 z){  // z * (i*SGN)
    return (SGN > 0) ? make_float2(-z.y, z.x) : make_float2(z.y, -z.x);
}

template<int SGN>
__device__ __forceinline__ void dft8(float2* v)
{
    const float C = 0.70710678118654752440f;
    const float S = (float)SGN;
    float2 u0 = f2add(v[0], v[4]), w0 = f2sub(v[0], v[4]);
    float2 u1 = f2add(v[1], v[5]), w1 = f2sub(v[1], v[5]);
    float2 u2 = f2add(v[2], v[6]), w2 = f2sub(v[2], v[6]);
    float2 u3 = f2add(v[3], v[7]), w3 = f2sub(v[3], v[7]);
    w1 = make_float2(C * (w1.x - S * w1.y),  C * (S * w1.x + w1.y));
    w2 = mul_is<SGN>(w2);
    w3 = make_float2(-C * (w3.x + S * w3.y), C * (S * w3.x - w3.y));
    float2 p0 = f2add(u0, u2), q0 = f2sub(u0, u2);
    float2 p1 = f2add(u1, u3), q1 = mul_is<SGN>(f2sub(u1, u3));
    v[0] = f2add(p0, p1); v[4] = f2sub(p0, p1);
    v[2] = f2add(q0, q1); v[6] = f2sub(q0, q1);
    float2 r0 = f2add(w0, w2), s0 = f2sub(w0, w2);
    float2 r1 = f2add(w1, w3), s1 = mul_is<SGN>(f2sub(w1, w3));
    v[1] = f2add(r0, r1); v[5] = f2sub(r0, r1);
    v[3] = f2add(s0, s1); v[7] = f2sub(s0, s1);
}

// apply w_M^(SGN*a*j) to v[j], j=1..7 — powers built as a depth-3 tree
template<int SGN, int M>
__device__ __forceinline__ void twiddles(float2* v, int a)
{
    const float kAng = (float)SGN * 6.283185307179586f / (float)M;
    float sn, cs;
    __sincosf(kAng * (float)a, &sn, &cs);
    float2 w1 = make_float2(cs, sn);
    float2 w2 = cmulf(w1, w1);
    float2 w3 = cmulf(w2, w1);
    float2 w4 = cmulf(w2, w2);
    float2 w5 = cmulf(w3, w2);
    float2 w6 = cmulf(w3, w3);
    float2 w7 = cmulf(w4, w3);
    v[1] = cmulf(v[1], w1); v[2] = cmulf(v[2], w2);
    v[3] = cmulf(v[3], w3); v[4] = cmulf(v[4], w4);
    v[5] = cmulf(v[5], w5); v[6] = cmulf(v[6], w6);
    v[7] = cmulf(v[7], w7);
}

// one radix-8 pass in shared memory (float2 interleaved, in-place per thread).
template<int SGN, int H>
__device__ __forceinline__ void stage_sh(float2* s, int t)
{
    const int M = 8 * H;
    int base = (t / H) * M + (t % H);
    int a    = t % H;
    float2 v[8];
    #pragma unroll
    for (int i = 0; i < 8; i++)
        v[i] = s[SIDX(base + H * i)];
    if (SGN < 0) { dft8<SGN>(v); twiddles<SGN, M>(v, a); }
    else         { twiddles<SGN, M>(v, a); dft8<SGN>(v); }
    #pragma unroll
    for (int i = 0; i < 8; i++)
        s[SIDX(base + H * i)] = v[i];
}

// ---------------- main kernel: 2 real channels per block ----------------
__global__ __launch_bounds__(TPB, 2)
void s4_fftconv_kernel(const float* __restrict__ x, float* __restrict__ y)
{
    __shared__ float2 s[LSEQ + (LSEQ >> 3)];
    const int t = threadIdx.x;
    const size_t base = (size_t)blockIdx.x * 2u * LSEQ;
    const float* x1 = x + base;
    const float* x2 = x + base + LSEQ;
    float* y1 = y + base;
    float* y2 = y + base + LSEQ;

    float2 v[8];

    // ---- forward stage 0 (M=4096, H=512): global -> regs -> shared
    #pragma unroll
    for (int b = 0; b < 8; b++)
        v[b] = make_float2(x1[t + 512 * b], x2[t + 512 * b]);
    dft8<-1>(v);
    twiddles<-1, 4096>(v, t);
    #pragma unroll
    for (int j = 0; j < 8; j++)
        s[SIDX(t + 512 * j)] = v[j];
    __syncthreads();

    stage_sh<-1, 64>(s, t);   // forward stage 1 (M=512)
    __syncthreads();
    stage_sh<-1, 8>(s, t);    // forward stage 2 (M=64)
    __syncthreads();

    // ---- fused: fwd stage 3 (H=1) + pointwise Ksp + inv stage 3 — in regs
    {
        const int i0 = 8 * t;
        const int p0 = SIDX(i0);          // 8 consecutive padded slots
        #pragma unroll
        for (int j = 0; j < 8; j++)
            v[j] = s[p0 + j];
        dft8<-1>(v);
        #pragma unroll
        for (int j = 0; j < 8; j++)
            v[j] = cmulf(v[j], __ldg(&g_Ksp[i0 + j]));
        dft8<1>(v);
        #pragma unroll
        for (int j = 0; j < 8; j++)
            s[p0 + j] = v[j];
    }
    __syncthreads();

    stage_sh<1, 8>(s, t);     // inverse stage 2
    __syncthreads();
    stage_sh<1, 64>(s, t);    // inverse stage 1
    __syncthreads();

    // ---- inverse stage 0 (M=4096, H=512): shared -> regs -> global
    #pragma unroll
    for (int j = 0; j < 8; j++)
        v[j] = s[SIDX(t + 512 * j)];
    twiddles<1, 4096>(v, t);
    dft8<1>(v);
    #pragma unroll
    for (int b = 0; b < 8; b++) {
        y1[t + 512 * b] = v[b].x;
        y2[t + 512 * b] = v[b].y;
    }
}

extern "C" void kernel_launch(void* const* d_in, const int* in_sizes, int n_in,
                              void* d_out, int out_size)
{
    const float* x   = (const float*)d_in[0];
    const float* lre = (const float*)d_in[1];
    const float* lim = (const float*)d_in[2];
    const float* pre = (const float*)d_in[3];
    const float* pim = (const float*)d_in[4];
    const float* bre = (const float*)d_in[5];
    const float* bim = (const float*)d_in[6];
    const float* cre = (const float*)d_in[7];
    const float* cim = (const float*)d_in[8];
    float* y = (float*)d_out;

    // (LSEQ/2 + 1) groups of 8 lanes
    compute_K_fused<<<(((LSEQ / 2 + 1) * 8) + 255) / 256, 256>>>(lre, lim, pre, pim, bre, bim, cre, cim);
    s4_fftconv_kernel<<<NPAIR, TPB>>>(x, y);
}